// round 16
// baseline (speedup 1.0000x reference)
#include <cuda_runtime.h>
#include <cuda_bf16.h>
#include <cstdint>
#include <math.h>

// Problem constants
#define T_    64
#define B_    256
#define FEAT_ 924
#define H_    512
#define NC_   151
#define ED_   100
#define KIN_  (FEAT_ + ED_)   // 1024
#define SIXH_ (6 * H_)        // 3072
#define M_TOT (T_ * B_)       // 16384

#define NCTA_  128            // persistent recurrence grid (4 groups x 32)

// ---------------------------------------------------------------------------
// Scratch (static device globals; zero-initialized at load)
// ---------------------------------------------------------------------------
__device__ __nv_bfloat16 g_TIhi[(size_t)M_TOT * KIN_];
__device__ __nv_bfloat16 g_TIlo[(size_t)M_TOT * KIN_];
__device__ __nv_bfloat16 g_Wihi[(size_t)SIXH_ * KIN_];
__device__ __nv_bfloat16 g_Wilo[(size_t)SIXH_ * KIN_];
__device__ __nv_bfloat16 g_Wohi[256 * H_];          // rows 151..255 stay zero
__device__ __nv_bfloat16 g_Wolo[256 * H_];
__device__ float g_PI[(size_t)M_TOT * SIXH_];
__device__ __nv_bfloat16 g_Hallhi[(size_t)M_TOT * H_];
__device__ __nv_bfloat16 g_Halllo[(size_t)M_TOT * H_];

// per-b-group barrier state
__device__ unsigned g_arr4[4 * 32];
__device__ unsigned g_gen4[4 * 32];

// ---------------------------------------------------------------------------
// PTX helpers (compute_103-safe)
// ---------------------------------------------------------------------------
__device__ __forceinline__ uint32_t smem_u32(const void* p) {
    uint32_t a;
    asm("{ .reg .u64 t; cvta.to.shared.u64 t, %1; cvt.u32.u64 %0, t; }" : "=r"(a) : "l"(p));
    return a;
}

#define CP_ASYNC16(dst, src) \
    asm volatile("cp.async.cg.shared.global [%0], [%1], 16;" :: "r"(dst), "l"(src) : "memory")
#define CP_COMMIT() asm volatile("cp.async.commit_group;" ::: "memory")
#define CP_WAIT(n)  asm volatile("cp.async.wait_group %0;" :: "n"(n) : "memory")
#define BAR_SYNC(id, cnt) \
    asm volatile("bar.sync %0, %1;" :: "r"(id), "r"(cnt) : "memory")

__device__ __forceinline__ void ldsm4(uint32_t* r, uint32_t addr) {
    asm volatile("ldmatrix.sync.aligned.m8n8.x4.shared.b16 {%0,%1,%2,%3}, [%4];"
                 : "=r"(r[0]), "=r"(r[1]), "=r"(r[2]), "=r"(r[3]) : "r"(addr));
}

__device__ __forceinline__ void mma16816(float* d, const uint32_t* a, const uint32_t* b) {
    asm volatile(
        "mma.sync.aligned.m16n8k16.row.col.f32.bf16.bf16.f32 "
        "{%0,%1,%2,%3}, {%4,%5,%6,%7}, {%8,%9}, {%0,%1,%2,%3};"
        : "+f"(d[0]), "+f"(d[1]), "+f"(d[2]), "+f"(d[3])
        : "r"(a[0]), "r"(a[1]), "r"(a[2]), "r"(a[3]), "r"(b[0]), "r"(b[1]));
}

// ---------------------------------------------------------------------------
// Split helpers: fp32 -> (bf16 hi, bf16 lo)
// ---------------------------------------------------------------------------
union BF4 { __nv_bfloat16 b[4]; uint2 u; };

__device__ __forceinline__ void split4(const float4 v, uint2* hi, uint2* lo) {
    BF4 Hh, Ll;
#pragma unroll
    for (int i = 0; i < 4; i++) {
        float f = (&v.x)[i];
        __nv_bfloat16 h = __float2bfloat16_rn(f);
        Hh.b[i] = h;
        Ll.b[i] = __float2bfloat16_rn(f - __bfloat162float(h));
    }
    *hi = Hh.u; *lo = Ll.u;
}

__global__ void k_concat_split(const float* __restrict__ x,
                               const int*   __restrict__ labels,
                               const float* __restrict__ embed) {
    const int C4 = KIN_ / 4;
    int idx = blockIdx.x * blockDim.x + threadIdx.x;
    if (idx >= M_TOT * C4) return;
    int row = idx / C4;
    int c   = (idx % C4) * 4;
    float4 v;
    if (c < FEAT_) {
        v = *reinterpret_cast<const float4*>(x + (size_t)row * FEAT_ + c);
    } else {
        int lab = labels[row];
        v = *reinterpret_cast<const float4*>(embed + (size_t)lab * ED_ + (c - FEAT_));
    }
    uint2 hi, lo;
    split4(v, &hi, &lo);
    *reinterpret_cast<uint2*>(g_TIhi + (size_t)row * KIN_ + c) = hi;
    *reinterpret_cast<uint2*>(g_TIlo + (size_t)row * KIN_ + c) = lo;
}

__global__ void k_split_w(const float* __restrict__ Wi) {
    int idx = blockIdx.x * blockDim.x + threadIdx.x;
    if (idx >= SIXH_ * (KIN_ / 4)) return;
    size_t off = (size_t)idx * 4;
    float4 v = *reinterpret_cast<const float4*>(Wi + off);
    uint2 hi, lo;
    split4(v, &hi, &lo);
    *reinterpret_cast<uint2*>(g_Wihi + off) = hi;
    *reinterpret_cast<uint2*>(g_Wilo + off) = lo;
}

__global__ void k_split_wo(const float* __restrict__ Wo) {
    int idx = blockIdx.x * blockDim.x + threadIdx.x;
    if (idx >= NC_ * (H_ / 4)) return;
    size_t off = (size_t)idx * 4;
    float4 v = *reinterpret_cast<const float4*>(Wo + off);
    uint2 hi, lo;
    split4(v, &hi, &lo);
    *reinterpret_cast<uint2*>(g_Wohi + off) = hi;
    *reinterpret_cast<uint2*>(g_Wolo + off) = lo;
}

// ---------------------------------------------------------------------------
// mma.sync bf16 3-term-split GEMM: 128(M) x 128(N) CTA tile, BK=32,
//   256 threads = 8 warps (4m x 2n), warp tile 32 x 64 (best-measured shape).
//   Halves cp.async-per-mma vs the 64x128 tile (B panel re-read 24x fewer).
//   2-stage cp.async: WAIT -> sync -> prefetch -> compute. 2 CTAs/SM.
// ---------------------------------------------------------------------------
#define GT_    8192                    // one tile: 128 rows x 64B
#define STG_   (4 * GT_)               // Ahi, Alo, Bhi, Blo = 32768 per stage
#define SMOFF_ 1024

template<int KD, int CSTR, bool GUARD>
__global__ __launch_bounds__(256, 2)
void k_mmaG(const __nv_bfloat16* __restrict__ Ahi_g,
            const __nv_bfloat16* __restrict__ Alo_g,
            const __nv_bfloat16* __restrict__ Bhi_g,
            const __nv_bfloat16* __restrict__ Blo_g,
            const float* __restrict__ bias,
            float* __restrict__ C, int ntiles) {
    constexpr int NCH = KD / 32;
    extern __shared__ char smem[];
    const uint32_t sb = smem_u32(smem);
    const int tid = threadIdx.x;
    const int wid = tid >> 5;
    const int lid = tid & 31;

    const int mt = blockIdx.x / ntiles;
    const int nt = blockIdx.x % ntiles;
    const int m0 = mt * 128;
    const int n0 = nt * 128;

    float* s_bias = reinterpret_cast<float*>(smem);
    if (tid < 128) {
        int gn = n0 + tid;
        s_bias[tid] = (!GUARD || gn < NC_) ? bias[gn] : 0.f;
    }

    const __nv_bfloat16* __restrict__ Ahi = Ahi_g + (size_t)m0 * KD;
    const __nv_bfloat16* __restrict__ Alo = Alo_g + (size_t)m0 * KD;
    const __nv_bfloat16* __restrict__ Bhi = Bhi_g + (size_t)n0 * KD;
    const __nv_bfloat16* __restrict__ Blo = Blo_g + (size_t)n0 * KD;

    // loader: each tile = 512 16B-lines (128 rows x 4 cols); 2 lines/thread/tile
    auto load_stage = [&](int ch, int stage) {
        const int k0 = ch * 32;
        const uint32_t base = sb + SMOFF_ + stage * STG_;
#pragma unroll
        for (int s = 0; s < 2; s++) {
            int e = s * 256 + tid;
            int row = e >> 2, c = e & 3;
            uint32_t soff = (uint32_t)(row * 64 + ((c ^ ((row >> 1) & 3)) * 16));
            size_t goff = (size_t)row * KD + k0 + c * 8;
            CP_ASYNC16(base + 0 * GT_ + soff, Ahi + goff);
            CP_ASYNC16(base + 1 * GT_ + soff, Alo + goff);
            CP_ASYNC16(base + 2 * GT_ + soff, Bhi + goff);
            CP_ASYNC16(base + 3 * GT_ + soff, Blo + goff);
        }
        CP_COMMIT();
    };

    const int wm = wid >> 1;                       // 0..3 (32 rows each)
    const int wn = wid & 1;                        // 0..1 (64 cols each)
    const int lrow = lid & 15;
    const int lhalf = lid >> 4;
    const int aswz = (lrow >> 1) & 3;

    float acc[2][8][4];
#pragma unroll
    for (int i = 0; i < 2; i++)
#pragma unroll
        for (int j = 0; j < 8; j++)
#pragma unroll
            for (int r = 0; r < 4; r++) acc[i][j][r] = 0.f;

    load_stage(0, 0);

    int stage = 0;
    for (int ch = 0; ch < NCH; ch++) {
        CP_WAIT(0);
        __syncthreads();
        if (ch + 1 < NCH) load_stage(ch + 1, stage ^ 1);

        const uint32_t base = sb + SMOFF_ + stage * STG_;
        const uint32_t aHi = base + 0 * GT_;
        const uint32_t aLo = base + 1 * GT_;
        const uint32_t bHi = base + 2 * GT_;
        const uint32_t bLo = base + 3 * GT_;

#pragma unroll
        for (int ks = 0; ks < 2; ks++) {
            const uint32_t coff = (uint32_t)(((ks * 2 + lhalf) ^ aswz) * 16);

            uint32_t a_hi[2][4], a_lo[2][4];
#pragma unroll
            for (int mf = 0; mf < 2; mf++) {
                uint32_t roff = (uint32_t)((wm * 32 + mf * 16 + lrow) * 64) + coff;
                ldsm4(a_hi[mf], aHi + roff);
                ldsm4(a_lo[mf], aLo + roff);
            }
            uint32_t b_hi[4][4], b_lo[4][4];
#pragma unroll
            for (int np = 0; np < 4; np++) {
                uint32_t roff = (uint32_t)((wn * 64 + np * 16 + lrow) * 64) + coff;
                ldsm4(b_hi[np], bHi + roff);
                ldsm4(b_lo[np], bLo + roff);
            }

#pragma unroll
            for (int mf = 0; mf < 2; mf++) {
#pragma unroll
                for (int np = 0; np < 4; np++) {
#pragma unroll
                    for (int q = 0; q < 2; q++) {
                        uint32_t bh[2] = {b_hi[np][q], b_hi[np][q + 2]};
                        uint32_t bl[2] = {b_lo[np][q], b_lo[np][q + 2]};
                        float* d = acc[mf][np * 2 + q];
                        mma16816(d, a_hi[mf], bh);
                        mma16816(d, a_hi[mf], bl);
                        mma16816(d, a_lo[mf], bh);
                    }
                }
            }
        }
        stage ^= 1;
    }

    const int trow = lid >> 2;
    const int tcol2 = (lid & 3) * 2;
#pragma unroll
    for (int mf = 0; mf < 2; mf++) {
        int m = m0 + wm * 32 + mf * 16 + trow;
        float* __restrict__ o0 = C + (size_t)m * CSTR + n0;
        float* __restrict__ o1 = C + (size_t)(m + 8) * CSTR + n0;
#pragma unroll
        for (int nf = 0; nf < 8; nf++) {
            int cn = wn * 64 + nf * 8 + tcol2;
            float b0 = s_bias[cn], b1 = s_bias[cn + 1];
            if (!GUARD) {
                float2 v0 = make_float2(acc[mf][nf][0] + b0, acc[mf][nf][1] + b1);
                float2 v1 = make_float2(acc[mf][nf][2] + b0, acc[mf][nf][3] + b1);
                *reinterpret_cast<float2*>(o0 + cn) = v0;
                *reinterpret_cast<float2*>(o1 + cn) = v1;
            } else {
                int gn = n0 + cn;
                if (gn < NC_)     { o0[cn]     = acc[mf][nf][0] + b0; o1[cn]     = acc[mf][nf][2] + b0; }
                if (gn + 1 < NC_) { o0[cn + 1] = acc[mf][nf][1] + b1; o1[cn + 1] = acc[mf][nf][3] + b1; }
            }
        }
    }
}

// ---------------------------------------------------------------------------
// Persistent tensor-core recurrence — EXACT R9 version (best measured).
//   K-split x2 (512 threads), chunk=32, 3 buffers/half, per-group barriers.
// ---------------------------------------------------------------------------
__device__ __forceinline__ float sigmoidf_(float x) {
    return 1.f / (1.f + __expf(-x));
}

#define WS2_TILEB (80 * 1024)             // 81920 per copy
#define HS2_STRIDE 80
#define HS2_TILEB  (64 * HS2_STRIDE)      // 5120 per (hi|lo)
#define HS2_BUFB   (2 * HS2_TILEB)        // 10240 per buffer
#define SM_H2_OFF  (2 * WS2_TILEB)        // 163840
#define SMEM_RECUR2 (SM_H2_OFF + 6 * HS2_BUFB)   // 225280

__global__ __launch_bounds__(512, 1)
void k_recur_mma(const float* __restrict__ Ws,
                 const float* __restrict__ bs,
                 const float* __restrict__ mask)
{
    extern __shared__ char smem[];
    const uint32_t sb = smem_u32(smem);
    const int tid = threadIdx.x;
    const int wid = tid >> 5;
    const int lid = tid & 31;

    const int nt = blockIdx.x & 31;
    const int bt = blockIdx.x >> 5;
    const int n0 = nt * 16;
    const int b0 = bt * 64;

    const int kh   = wid >> 3;            // K-half: 0 or 1
    const int wid7 = wid & 7;
    const int wm = wid7 >> 1;             // 0..3 (16 rows each)
    const int wn = wid7 & 1;              // 0..1 (8 cols per gate each)

    unsigned* const p_arr = &g_arr4[bt * 32];
    unsigned* const p_gen = &g_gen4[bt * 32];

    __shared__ unsigned s_base;
    if (tid == 0) {
        unsigned v;
        asm volatile("ld.acquire.gpu.global.u32 %0, [%1];" : "=r"(v) : "l"(p_gen));
        s_base = v;
    }

    // ---- preload + split Ws slice (80 rows x 512 k), XOR line-swizzle
    for (int s = tid; s < 80 * 128; s += 512) {
        int r  = s >> 7;
        int c4 = s & 127;
        int g  = r >> 4, j = r & 15;
        float4 v = *reinterpret_cast<const float4*>(
            Ws + (size_t)(g * H_ + n0 + j) * H_ + c4 * 4);
        uint2 hi, lo;
        split4(v, &hi, &lo);
        int c16 = c4 >> 1;
        int sl  = c16 ^ (r & 7);
        uint32_t off = (uint32_t)r * 1024 + sl * 16 + (c4 & 1) * 8;
        *reinterpret_cast<uint2*>(smem + off) = hi;
        *reinterpret_cast<uint2*>(smem + WS2_TILEB + off) = lo;
    }

    // ---- B-frag row addressing (per gate pair p)
    const int gA[3] = {0, 2, 4};
    const int gB[3] = {1, 3, 4};
    uint32_t browbase[3];
    uint32_t brow7[3];
#pragma unroll
    for (int p = 0; p < 3; p++) {
        int g = ((lid >> 3) & 1) ? gB[p] : gA[p];
        int rowB = g * 16 + wn * 8 + (lid & 7);
        browbase[p] = (uint32_t)rowB * 1024;
        brow7[p]    = (uint32_t)(rowB & 7);
    }
    const int lhalf = lid >> 4;
    const uint32_t abase = (uint32_t)((wm * 16 + (lid & 15)) * HS2_STRIDE) + lhalf * 16;
    const uint32_t klbase = (uint32_t)(kh * 32);   // k-line base for this half

    // ---- epilogue constants (lower half owns outputs)
    const int r0 = b0 + wm * 16 + (lid >> 2);
    const int c0 = n0 + wn * 8 + (lid & 3) * 2;
    float2 bs2[5];
    float2 mk[2];
    float2 cst[2] = {{0.f, 0.f}, {0.f, 0.f}};
    if (kh == 0) {
#pragma unroll
        for (int g = 0; g < 5; g++) bs2[g] = *reinterpret_cast<const float2*>(bs + g * H_ + c0);
        mk[0] = *reinterpret_cast<const float2*>(mask + (size_t)r0 * H_ + c0);
        mk[1] = *reinterpret_cast<const float2*>(mask + (size_t)(r0 + 8) * H_ + c0);
    }

    __syncthreads();
    const unsigned base = s_base;

    // h-chunk loader: each half's 256 threads load their half's chunks
    const int t256 = tid & 255;
    const int hrow = t256 >> 2;            // 0..63
    const int hcol = t256 & 3;             // 16B col 0..3
    const int kb   = kh * 256;             // this half's K base (elements)

    auto load_hchunk = [&](int kc, int buf,
                           const __nv_bfloat16* __restrict__ Hhi,
                           const __nv_bfloat16* __restrict__ Hlo) {
        uint32_t db = sb + SM_H2_OFF + (kh * 3 + buf) * HS2_BUFB;
        size_t goff = (size_t)(b0 + hrow) * H_ + kb + kc * 32 + hcol * 8;
        uint32_t soff = (uint32_t)(hrow * HS2_STRIDE + hcol * 16);
        CP_ASYNC16(db + soff, Hhi + goff);
        CP_ASYNC16(db + HS2_TILEB + soff, Hlo + goff);
        CP_COMMIT();
    };

    float* ex = reinterpret_cast<float*>(smem + SM_H2_OFF);   // aliases h bufs

    for (int t = 0; t < T_; t++) {
        float acc[5][4];
#pragma unroll
        for (int g = 0; g < 5; g++)
#pragma unroll
            for (int r = 0; r < 4; r++) acc[g][r] = 0.f;

        // prefetch pi (lower half only)
        float2 pf[2][6];
        if (kh == 0) {
            const float* __restrict__ piB = g_PI + (size_t)t * B_ * SIXH_;
#pragma unroll
            for (int i = 0; i < 2; i++) {
                const float* pir = piB + (size_t)(r0 + i * 8) * SIXH_ + c0;
#pragma unroll
                for (int g = 0; g < 6; g++)
                    pf[i][g] = *reinterpret_cast<const float2*>(pir + g * H_);
            }
        }

        if (t > 0) {
            const __nv_bfloat16* __restrict__ Hhi = g_Hallhi + (size_t)(t - 1) * B_ * H_;
            const __nv_bfloat16* __restrict__ Hlo = g_Halllo + (size_t)(t - 1) * B_ * H_;

            load_hchunk(0, 0, Hhi, Hlo);
            load_hchunk(1, 1, Hhi, Hlo);

            int stage = 0;
            for (int kc = 0; kc < 8; kc++) {
                if (kc + 1 < 8) { CP_WAIT(1); } else { CP_WAIT(0); }
                BAR_SYNC(1 + kh, 256);
                if (kc + 2 < 8) {
                    int s2 = stage - 1; if (s2 < 0) s2 += 3;
                    load_hchunk(kc + 2, s2, Hhi, Hlo);
                }

                const uint32_t hb_hi = sb + SM_H2_OFF + (kh * 3 + stage) * HS2_BUFB;
                const uint32_t hb_lo = hb_hi + HS2_TILEB;

#pragma unroll
                for (int ks = 0; ks < 2; ks++) {
                    uint32_t ahi[4], alo[4];
                    uint32_t aoff = abase + ks * 32;
                    ldsm4(ahi, hb_hi + aoff);
                    ldsm4(alo, hb_lo + aoff);
                    const uint32_t kline = klbase + kc * 4 + ks * 2 + lhalf;
#pragma unroll
                    for (int p = 0; p < 3; p++) {
                        uint32_t bh[4], bl[4];
                        uint32_t boff = browbase[p] + ((kline ^ brow7[p]) * 16);
                        ldsm4(bh, sb + boff);
                        ldsm4(bl, sb + WS2_TILEB + boff);
                        const int qmax = (p == 2) ? 1 : 2;
#pragma unroll
                        for (int q = 0; q < qmax; q++) {
                            const int g = 2 * p + q;
                            uint32_t bhf[2] = {bh[q], bh[q + 2]};
                            uint32_t blf[2] = {bl[q], bl[q + 2]};
                            mma16816(acc[g], ahi, bhf);
                            mma16816(acc[g], ahi, blf);
                            mma16816(acc[g], alo, bhf);
                        }
                    }
                }
                if (++stage == 3) stage = 0;
            }

            // ---- K-split reduction: upper half -> smem -> lower half adds
            __syncthreads();
            if (kh == 1) {
                float* e = ex + (size_t)t256 * 20;
#pragma unroll
                for (int g = 0; g < 5; g++)
                    *reinterpret_cast<float4*>(e + g * 4) =
                        *reinterpret_cast<float4*>(&acc[g][0]);
            }
            __syncthreads();
            if (kh == 0) {
                const float* e = ex + (size_t)t256 * 20;
#pragma unroll
                for (int g = 0; g < 5; g++) {
                    float4 v = *reinterpret_cast<const float4*>(e + g * 4);
                    acc[g][0] += v.x; acc[g][1] += v.y;
                    acc[g][2] += v.z; acc[g][3] += v.w;
                }
            }
        }

        // ---- epilogue (lower half): gates + cell + highway + dropout
        if (kh == 0) {
            __nv_bfloat16* __restrict__ hhi = g_Hallhi + (size_t)t * B_ * H_;
            __nv_bfloat16* __restrict__ hlo = g_Halllo + (size_t)t * B_ * H_;
#pragma unroll
            for (int i = 0; i < 2; i++) {
                const int r = r0 + i * 8;
                float igx = sigmoidf_(pf[i][0].x + acc[0][2 * i + 0] + bs2[0].x);
                float igy = sigmoidf_(pf[i][0].y + acc[0][2 * i + 1] + bs2[0].y);
                float fgx = sigmoidf_(pf[i][1].x + acc[1][2 * i + 0] + bs2[1].x);
                float fgy = sigmoidf_(pf[i][1].y + acc[1][2 * i + 1] + bs2[1].y);
                float mix = tanhf   (pf[i][2].x + acc[2][2 * i + 0] + bs2[2].x);
                float miy = tanhf   (pf[i][2].y + acc[2][2 * i + 1] + bs2[2].y);
                float ogx = sigmoidf_(pf[i][3].x + acc[3][2 * i + 0] + bs2[3].x);
                float ogy = sigmoidf_(pf[i][3].y + acc[3][2 * i + 1] + bs2[3].y);
                float hgx = sigmoidf_(pf[i][4].x + acc[4][2 * i + 0] + bs2[4].x);
                float hgy = sigmoidf_(pf[i][4].y + acc[4][2 * i + 1] + bs2[4].y);

                float cnx = igx * mix + fgx * cst[i].x;
                float cny = igy * miy + fgy * cst[i].y;
                float ox = ogx * tanhf(cnx);
                float oy = ogy * tanhf(cny);
                ox = hgx * ox + (1.f - hgx) * pf[i][5].x;
                oy = hgy * oy + (1.f - hgy) * pf[i][5].y;
                ox *= mk[i].x;
                oy *= mk[i].y;
                cst[i].x = cnx;
                cst[i].y = cny;

                __nv_bfloat16 hx = __float2bfloat16_rn(ox);
                __nv_bfloat16 hy = __float2bfloat16_rn(oy);
                __nv_bfloat16 lx = __float2bfloat16_rn(ox - __bfloat162float(hx));
                __nv_bfloat16 ly = __float2bfloat16_rn(oy - __bfloat162float(hy));
                uint32_t ph = (uint32_t)__bfloat16_as_ushort(hy) << 16 | __bfloat16_as_ushort(hx);
                uint32_t pl = (uint32_t)__bfloat16_as_ushort(ly) << 16 | __bfloat16_as_ushort(lx);
                *reinterpret_cast<uint32_t*>(hhi + (size_t)r * H_ + c0) = ph;
                *reinterpret_cast<uint32_t*>(hlo + (size_t)r * H_ + c0) = pl;
            }
        }

        // ---- per-group barrier (32 CTAs)
        if (t < T_ - 1) {
            __syncthreads();
            if (tid == 0) {
                __threadfence();
                unsigned prev = atomicAdd(p_arr, 1);
                if (prev == 31) {
                    *p_arr = 0;
                    __threadfence();
                    atomicAdd(p_gen, 1);
                } else {
                    unsigned target = base + (unsigned)t + 1u;
                    unsigned v;
                    do {
                        asm volatile("ld.acquire.gpu.global.u32 %0, [%1];"
                                     : "=r"(v) : "l"(p_gen));
                    } while (v - base < target - base);
                }
            }
            __syncthreads();
        }
    }
}

// ---------------------------------------------------------------------------
// kernel_launch
// Input order: x, labels, embed, Wi, bi, Ws, bs, Wo, bo, mask
// ---------------------------------------------------------------------------
extern "C" void kernel_launch(void* const* d_in, const int* in_sizes, int n_in,
                              void* d_out, int out_size) {
    const float* x      = (const float*)d_in[0];
    const int*   labels = (const int*)  d_in[1];
    const float* embed  = (const float*)d_in[2];
    const float* Wi     = (const float*)d_in[3];
    const float* bi     = (const float*)d_in[4];
    const float* Ws     = (const float*)d_in[5];
    const float* bs     = (const float*)d_in[6];
    const float* Wo     = (const float*)d_in[7];
    const float* bo     = (const float*)d_in[8];
    const float* mask   = (const float*)d_in[9];
    float* out = (float*)d_out;

    __nv_bfloat16 *tihi, *tilo, *wihi, *wilo, *wohi, *wolo, *hhi, *hlo;
    float* pi;
    cudaGetSymbolAddress((void**)&tihi, g_TIhi);
    cudaGetSymbolAddress((void**)&tilo, g_TIlo);
    cudaGetSymbolAddress((void**)&wihi, g_Wihi);
    cudaGetSymbolAddress((void**)&wilo, g_Wilo);
    cudaGetSymbolAddress((void**)&wohi, g_Wohi);
    cudaGetSymbolAddress((void**)&wolo, g_Wolo);
    cudaGetSymbolAddress((void**)&hhi,  g_Hallhi);
    cudaGetSymbolAddress((void**)&hlo,  g_Halllo);
    cudaGetSymbolAddress((void**)&pi,   g_PI);

    // 1) splits
    {
        int total = SIXH_ * (KIN_ / 4);
        k_split_w<<<(total + 255) / 256, 256>>>(Wi);
    }
    {
        int total = NC_ * (H_ / 4);
        k_split_wo<<<(total + 255) / 256, 256>>>(Wo);
    }
    {
        int total = M_TOT * (KIN_ / 4);
        k_concat_split<<<(total + 255) / 256, 256>>>(x, labels, embed);
    }
    // 2) PI = TI @ Wi^T + bi  (128x128 tiles, warp 32x64, 2 CTAs/SM)
    {
        const int smem_bytes = SMOFF_ + 2 * STG_;   // 1024 + 64KB
        cudaFuncSetAttribute(k_mmaG<KIN_, SIXH_, false>,
                             cudaFuncAttributeMaxDynamicSharedMemorySize, smem_bytes);
        dim3 grid((M_TOT / 128) * (SIXH_ / 128));   // 128 * 24 = 3072
        k_mmaG<KIN_, SIXH_, false><<<grid, 256, smem_bytes>>>(
            tihi, tilo, wihi, wilo, bi, pi, SIXH_ / 128);
    }
    // 3) persistent recurrence (exact R9 — best measured)
    {
        cudaFuncSetAttribute(k_recur_mma, cudaFuncAttributeMaxDynamicSharedMemorySize, SMEM_RECUR2);
        k_recur_mma<<<NCTA_, 512, SMEM_RECUR2>>>(Ws, bs, mask);
    }
    // 4) OUT = H_all @ Wo^T + bo
    {
        const int smem_bytes = SMOFF_ + 2 * STG_;
        cudaFuncSetAttribute(k_mmaG<H_, NC_, true>,
                             cudaFuncAttributeMaxDynamicSharedMemorySize, smem_bytes);
        dim3 grid((M_TOT / 128) * 2);               // 256
        k_mmaG<H_, NC_, true><<<grid, 256, smem_bytes>>>(
            hhi, hlo, wohi, wolo, bo, out, 2);
    }
}

// round 17
// speedup vs baseline: 1.0498x; 1.0498x over previous
#include <cuda_runtime.h>
#include <cuda_bf16.h>
#include <cstdint>
#include <math.h>

// Problem constants
#define T_    64
#define B_    256
#define FEAT_ 924
#define H_    512
#define NC_   151
#define ED_   100
#define KIN_  (FEAT_ + ED_)   // 1024
#define SIXH_ (6 * H_)        // 3072
#define M_TOT (T_ * B_)       // 16384

#define NCTA_  128            // persistent recurrence grid (4 groups x 32)

// ---------------------------------------------------------------------------
// Scratch (static device globals; zero-initialized at load)
// ---------------------------------------------------------------------------
__device__ __nv_bfloat16 g_TIhi[(size_t)M_TOT * KIN_];
__device__ __nv_bfloat16 g_TIlo[(size_t)M_TOT * KIN_];
__device__ __nv_bfloat16 g_Wihi[(size_t)SIXH_ * KIN_];
__device__ __nv_bfloat16 g_Wilo[(size_t)SIXH_ * KIN_];
__device__ __nv_bfloat16 g_Wohi[256 * H_];          // rows 151..255 stay zero
__device__ __nv_bfloat16 g_Wolo[256 * H_];
__device__ float g_PI[(size_t)M_TOT * SIXH_];
__device__ __nv_bfloat16 g_Hallhi[(size_t)M_TOT * H_];
__device__ __nv_bfloat16 g_Halllo[(size_t)M_TOT * H_];

// per-b-group MONOTONIC barrier counters (128B apart)
__device__ unsigned g_cnt4[4 * 32];

// ---------------------------------------------------------------------------
// PTX helpers (compute_103-safe)
// ---------------------------------------------------------------------------
__device__ __forceinline__ uint32_t smem_u32(const void* p) {
    uint32_t a;
    asm("{ .reg .u64 t; cvta.to.shared.u64 t, %1; cvt.u32.u64 %0, t; }" : "=r"(a) : "l"(p));
    return a;
}

#define CP_ASYNC16(dst, src) \
    asm volatile("cp.async.cg.shared.global [%0], [%1], 16;" :: "r"(dst), "l"(src) : "memory")
#define CP_COMMIT() asm volatile("cp.async.commit_group;" ::: "memory")
#define CP_WAIT(n)  asm volatile("cp.async.wait_group %0;" :: "n"(n) : "memory")
#define BAR_SYNC(id, cnt) \
    asm volatile("bar.sync %0, %1;" :: "r"(id), "r"(cnt) : "memory")

__device__ __forceinline__ void ldsm4(uint32_t* r, uint32_t addr) {
    asm volatile("ldmatrix.sync.aligned.m8n8.x4.shared.b16 {%0,%1,%2,%3}, [%4];"
                 : "=r"(r[0]), "=r"(r[1]), "=r"(r[2]), "=r"(r[3]) : "r"(addr));
}

__device__ __forceinline__ void mma16816(float* d, const uint32_t* a, const uint32_t* b) {
    asm volatile(
        "mma.sync.aligned.m16n8k16.row.col.f32.bf16.bf16.f32 "
        "{%0,%1,%2,%3}, {%4,%5,%6,%7}, {%8,%9}, {%0,%1,%2,%3};"
        : "+f"(d[0]), "+f"(d[1]), "+f"(d[2]), "+f"(d[3])
        : "r"(a[0]), "r"(a[1]), "r"(a[2]), "r"(a[3]), "r"(b[0]), "r"(b[1]));
}

// ---------------------------------------------------------------------------
// Split helpers: fp32 -> (bf16 hi, bf16 lo)
// ---------------------------------------------------------------------------
union BF4 { __nv_bfloat16 b[4]; uint2 u; };

__device__ __forceinline__ void split4(const float4 v, uint2* hi, uint2* lo) {
    BF4 Hh, Ll;
#pragma unroll
    for (int i = 0; i < 4; i++) {
        float f = (&v.x)[i];
        __nv_bfloat16 h = __float2bfloat16_rn(f);
        Hh.b[i] = h;
        Ll.b[i] = __float2bfloat16_rn(f - __bfloat162float(h));
    }
    *hi = Hh.u; *lo = Ll.u;
}

// One merged prep kernel: [0, NW) Wi split | [NW, NW+NWO) Wo split | rest concat
#define NW_   (SIXH_ * (KIN_ / 4))          // 786432
#define NWO_  (NC_ * (H_ / 4))              // 19328
#define NCC_  (M_TOT * (KIN_ / 4))          // 4194304
#define NPREP_ (NW_ + NWO_ + NCC_)

__global__ void k_prep(const float* __restrict__ x,
                       const int*   __restrict__ labels,
                       const float* __restrict__ embed,
                       const float* __restrict__ Wi,
                       const float* __restrict__ Wo) {
    int idx = blockIdx.x * blockDim.x + threadIdx.x;
    if (idx >= NPREP_) return;
    if (idx < NW_) {
        size_t off = (size_t)idx * 4;
        float4 v = *reinterpret_cast<const float4*>(Wi + off);
        uint2 hi, lo;
        split4(v, &hi, &lo);
        *reinterpret_cast<uint2*>(g_Wihi + off) = hi;
        *reinterpret_cast<uint2*>(g_Wilo + off) = lo;
    } else if (idx < NW_ + NWO_) {
        size_t off = (size_t)(idx - NW_) * 4;
        float4 v = *reinterpret_cast<const float4*>(Wo + off);
        uint2 hi, lo;
        split4(v, &hi, &lo);
        *reinterpret_cast<uint2*>(g_Wohi + off) = hi;
        *reinterpret_cast<uint2*>(g_Wolo + off) = lo;
    } else {
        int e = idx - NW_ - NWO_;
        const int C4 = KIN_ / 4;
        int row = e / C4;
        int c   = (e % C4) * 4;
        float4 v;
        if (c < FEAT_) {
            v = *reinterpret_cast<const float4*>(x + (size_t)row * FEAT_ + c);
        } else {
            int lab = labels[row];
            v = *reinterpret_cast<const float4*>(embed + (size_t)lab * ED_ + (c - FEAT_));
        }
        uint2 hi, lo;
        split4(v, &hi, &lo);
        *reinterpret_cast<uint2*>(g_TIhi + (size_t)row * KIN_ + c) = hi;
        *reinterpret_cast<uint2*>(g_TIlo + (size_t)row * KIN_ + c) = lo;
    }
}

// ---------------------------------------------------------------------------
// mma.sync bf16 3-term-split GEMM (R14/R15 config — best measured).
//   64(M) x 128(N) CTA tile, BK=32, 128 threads = 4 warps (2M x 2N),
//   warp tile 32 x 64. 2-stage cp.async: WAIT -> sync -> prefetch -> compute.
// ---------------------------------------------------------------------------
#define AT64_  4096                    // A tile (64 rows x 64B)
#define BT64_  8192                    // B tile (128 rows x 64B)
#define STG_   (2 * AT64_ + 2 * BT64_) // 24576 per stage
#define SMOFF_ 1024

template<int KD, int CSTR, bool GUARD>
__global__ __launch_bounds__(128, 4)
void k_mmaG(const __nv_bfloat16* __restrict__ Ahi_g,
            const __nv_bfloat16* __restrict__ Alo_g,
            const __nv_bfloat16* __restrict__ Bhi_g,
            const __nv_bfloat16* __restrict__ Blo_g,
            const float* __restrict__ bias,
            float* __restrict__ C, int ntiles) {
    constexpr int NCH = KD / 32;
    extern __shared__ char smem[];
    const uint32_t sb = smem_u32(smem);
    const int tid = threadIdx.x;
    const int wid = tid >> 5;
    const int lid = tid & 31;

    const int mt = blockIdx.x / ntiles;
    const int nt = blockIdx.x % ntiles;
    const int m0 = mt * 64;
    const int n0 = nt * 128;

    float* s_bias = reinterpret_cast<float*>(smem);
    if (tid < 128) {
        int gn = n0 + tid;
        s_bias[tid] = (!GUARD || gn < NC_) ? bias[gn] : 0.f;
    }

    const __nv_bfloat16* __restrict__ Ahi = Ahi_g + (size_t)m0 * KD;
    const __nv_bfloat16* __restrict__ Alo = Alo_g + (size_t)m0 * KD;
    const __nv_bfloat16* __restrict__ Bhi = Bhi_g + (size_t)n0 * KD;
    const __nv_bfloat16* __restrict__ Blo = Blo_g + (size_t)n0 * KD;

    auto load_stage = [&](int ch, int stage) {
        const int k0 = ch * 32;
        const uint32_t base = sb + SMOFF_ + stage * STG_;
#pragma unroll
        for (int s = 0; s < 2; s++) {
            int e = s * 128 + tid;
            int row = e >> 2, c = e & 3;
            uint32_t soff = (uint32_t)(row * 64 + ((c ^ ((row >> 1) & 3)) * 16));
            size_t goff = (size_t)row * KD + k0 + c * 8;
            CP_ASYNC16(base + 0 * AT64_ + soff, Ahi + goff);
            CP_ASYNC16(base + 1 * AT64_ + soff, Alo + goff);
        }
#pragma unroll
        for (int s = 0; s < 4; s++) {
            int e = s * 128 + tid;
            int row = e >> 2, c = e & 3;
            uint32_t soff = (uint32_t)(row * 64 + ((c ^ ((row >> 1) & 3)) * 16));
            size_t goff = (size_t)row * KD + k0 + c * 8;
            CP_ASYNC16(base + 2 * AT64_ + soff,          Bhi + goff);
            CP_ASYNC16(base + 2 * AT64_ + BT64_ + soff,  Blo + goff);
        }
        CP_COMMIT();
    };

    const int wm = wid >> 1;                       // 0..1 (32 rows each)
    const int wn = wid & 1;                        // 0..1 (64 cols each)
    const int lrow = lid & 15;
    const int lhalf = lid >> 4;
    const int aswz = (lrow >> 1) & 3;

    float acc[2][8][4];
#pragma unroll
    for (int i = 0; i < 2; i++)
#pragma unroll
        for (int j = 0; j < 8; j++)
#pragma unroll
            for (int r = 0; r < 4; r++) acc[i][j][r] = 0.f;

    load_stage(0, 0);

    int stage = 0;
    for (int ch = 0; ch < NCH; ch++) {
        CP_WAIT(0);
        __syncthreads();
        if (ch + 1 < NCH) load_stage(ch + 1, stage ^ 1);

        const uint32_t base = sb + SMOFF_ + stage * STG_;
        const uint32_t aHi = base + 0 * AT64_;
        const uint32_t aLo = base + 1 * AT64_;
        const uint32_t bHi = base + 2 * AT64_;
        const uint32_t bLo = bHi + BT64_;

#pragma unroll
        for (int ks = 0; ks < 2; ks++) {
            const uint32_t coff = (uint32_t)(((ks * 2 + lhalf) ^ aswz) * 16);

            uint32_t a_hi[2][4], a_lo[2][4];
#pragma unroll
            for (int mf = 0; mf < 2; mf++) {
                uint32_t roff = (uint32_t)((wm * 32 + mf * 16 + lrow) * 64) + coff;
                ldsm4(a_hi[mf], aHi + roff);
                ldsm4(a_lo[mf], aLo + roff);
            }
            uint32_t b_hi[4][4], b_lo[4][4];
#pragma unroll
            for (int np = 0; np < 4; np++) {
                uint32_t roff = (uint32_t)((wn * 64 + np * 16 + lrow) * 64) + coff;
                ldsm4(b_hi[np], bHi + roff);
                ldsm4(b_lo[np], bLo + roff);
            }

#pragma unroll
            for (int mf = 0; mf < 2; mf++) {
#pragma unroll
                for (int np = 0; np < 4; np++) {
#pragma unroll
                    for (int q = 0; q < 2; q++) {
                        uint32_t bh[2] = {b_hi[np][q], b_hi[np][q + 2]};
                        uint32_t bl[2] = {b_lo[np][q], b_lo[np][q + 2]};
                        float* d = acc[mf][np * 2 + q];
                        mma16816(d, a_hi[mf], bh);
                        mma16816(d, a_hi[mf], bl);
                        mma16816(d, a_lo[mf], bh);
                    }
                }
            }
        }
        stage ^= 1;
    }

    const int trow = lid >> 2;
    const int tcol2 = (lid & 3) * 2;
#pragma unroll
    for (int mf = 0; mf < 2; mf++) {
        int m = m0 + wm * 32 + mf * 16 + trow;
        float* __restrict__ o0 = C + (size_t)m * CSTR + n0;
        float* __restrict__ o1 = C + (size_t)(m + 8) * CSTR + n0;
#pragma unroll
        for (int nf = 0; nf < 8; nf++) {
            int cn = wn * 64 + nf * 8 + tcol2;
            float b0 = s_bias[cn], b1 = s_bias[cn + 1];
            if (!GUARD) {
                float2 v0 = make_float2(acc[mf][nf][0] + b0, acc[mf][nf][1] + b1);
                float2 v1 = make_float2(acc[mf][nf][2] + b0, acc[mf][nf][3] + b1);
                *reinterpret_cast<float2*>(o0 + cn) = v0;
                *reinterpret_cast<float2*>(o1 + cn) = v1;
            } else {
                int gn = n0 + cn;
                if (gn < NC_)     { o0[cn]     = acc[mf][nf][0] + b0; o1[cn]     = acc[mf][nf][2] + b0; }
                if (gn + 1 < NC_) { o0[cn + 1] = acc[mf][nf][1] + b1; o1[cn + 1] = acc[mf][nf][3] + b1; }
            }
        }
    }
}

// ---------------------------------------------------------------------------
// Persistent tensor-core recurrence — R9 pipeline (best measured) with:
//   (a) one-hop monotonic-counter barrier (no generation flag hop)
//   (b) h-chunk loads issued before the pi register prefetch
// ---------------------------------------------------------------------------
__device__ __forceinline__ float sigmoidf_(float x) {
    return 1.f / (1.f + __expf(-x));
}

#define WS2_TILEB (80 * 1024)             // 81920 per copy
#define HS2_STRIDE 80
#define HS2_TILEB  (64 * HS2_STRIDE)      // 5120 per (hi|lo)
#define HS2_BUFB   (2 * HS2_TILEB)        // 10240 per buffer
#define SM_H2_OFF  (2 * WS2_TILEB)        // 163840
#define SMEM_RECUR2 (SM_H2_OFF + 6 * HS2_BUFB)   // 225280

__global__ __launch_bounds__(512, 1)
void k_recur_mma(const float* __restrict__ Ws,
                 const float* __restrict__ bs,
                 const float* __restrict__ mask)
{
    extern __shared__ char smem[];
    const uint32_t sb = smem_u32(smem);
    const int tid = threadIdx.x;
    const int wid = tid >> 5;
    const int lid = tid & 31;

    const int nt = blockIdx.x & 31;
    const int bt = blockIdx.x >> 5;
    const int n0 = nt * 16;
    const int b0 = bt * 64;

    const int kh   = wid >> 3;            // K-half: 0 or 1
    const int wid7 = wid & 7;
    const int wm = wid7 >> 1;             // 0..3 (16 rows each)
    const int wn = wid7 & 1;              // 0..1 (8 cols per gate each)

    unsigned* const p_cnt = &g_cnt4[bt * 32];

    __shared__ unsigned s_base;
    if (tid == 0) {
        unsigned v;
        asm volatile("ld.acquire.gpu.global.u32 %0, [%1];" : "=r"(v) : "l"(p_cnt));
        s_base = v;
    }

    // ---- preload + split Ws slice (80 rows x 512 k), XOR line-swizzle
    for (int s = tid; s < 80 * 128; s += 512) {
        int r  = s >> 7;
        int c4 = s & 127;
        int g  = r >> 4, j = r & 15;
        float4 v = *reinterpret_cast<const float4*>(
            Ws + (size_t)(g * H_ + n0 + j) * H_ + c4 * 4);
        uint2 hi, lo;
        split4(v, &hi, &lo);
        int c16 = c4 >> 1;
        int sl  = c16 ^ (r & 7);
        uint32_t off = (uint32_t)r * 1024 + sl * 16 + (c4 & 1) * 8;
        *reinterpret_cast<uint2*>(smem + off) = hi;
        *reinterpret_cast<uint2*>(smem + WS2_TILEB + off) = lo;
    }

    // ---- B-frag row addressing (per gate pair p)
    const int gA[3] = {0, 2, 4};
    const int gB[3] = {1, 3, 4};
    uint32_t browbase[3];
    uint32_t brow7[3];
#pragma unroll
    for (int p = 0; p < 3; p++) {
        int g = ((lid >> 3) & 1) ? gB[p] : gA[p];
        int rowB = g * 16 + wn * 8 + (lid & 7);
        browbase[p] = (uint32_t)rowB * 1024;
        brow7[p]    = (uint32_t)(rowB & 7);
    }
    const int lhalf = lid >> 4;
    const uint32_t abase = (uint32_t)((wm * 16 + (lid & 15)) * HS2_STRIDE) + lhalf * 16;
    const uint32_t klbase = (uint32_t)(kh * 32);   // k-line base for this half

    // ---- epilogue constants (lower half owns outputs)
    const int r0 = b0 + wm * 16 + (lid >> 2);
    const int c0 = n0 + wn * 8 + (lid & 3) * 2;
    float2 bs2[5];
    float2 mk[2];
    float2 cst[2] = {{0.f, 0.f}, {0.f, 0.f}};
    if (kh == 0) {
#pragma unroll
        for (int g = 0; g < 5; g++) bs2[g] = *reinterpret_cast<const float2*>(bs + g * H_ + c0);
        mk[0] = *reinterpret_cast<const float2*>(mask + (size_t)r0 * H_ + c0);
        mk[1] = *reinterpret_cast<const float2*>(mask + (size_t)(r0 + 8) * H_ + c0);
    }

    __syncthreads();
    const unsigned base = s_base;

    // h-chunk loader: each half's 256 threads load their half's chunks
    const int t256 = tid & 255;
    const int hrow = t256 >> 2;            // 0..63
    const int hcol = t256 & 3;             // 16B col 0..3
    const int kb   = kh * 256;             // this half's K base (elements)

    auto load_hchunk = [&](int kc, int buf,
                           const __nv_bfloat16* __restrict__ Hhi,
                           const __nv_bfloat16* __restrict__ Hlo) {
        uint32_t db = sb + SM_H2_OFF + (kh * 3 + buf) * HS2_BUFB;
        size_t goff = (size_t)(b0 + hrow) * H_ + kb + kc * 32 + hcol * 8;
        uint32_t soff = (uint32_t)(hrow * HS2_STRIDE + hcol * 16);
        CP_ASYNC16(db + soff, Hhi + goff);
        CP_ASYNC16(db + HS2_TILEB + soff, Hlo + goff);
        CP_COMMIT();
    };

    float* ex = reinterpret_cast<float*>(smem + SM_H2_OFF);   // aliases h bufs

    for (int t = 0; t < T_; t++) {
        float acc[5][4];
#pragma unroll
        for (int g = 0; g < 5; g++)
#pragma unroll
            for (int r = 0; r < 4; r++) acc[g][r] = 0.f;

        const __nv_bfloat16* __restrict__ Hhi = g_Hallhi + (size_t)(t - 1) * B_ * H_;
        const __nv_bfloat16* __restrict__ Hlo = g_Halllo + (size_t)(t - 1) * B_ * H_;

        // critical-path h loads first
        if (t > 0) {
            load_hchunk(0, 0, Hhi, Hlo);
            load_hchunk(1, 1, Hhi, Hlo);
        }

        // pi register prefetch (lower half only)
        float2 pf[2][6];
        if (kh == 0) {
            const float* __restrict__ piB = g_PI + (size_t)t * B_ * SIXH_;
#pragma unroll
            for (int i = 0; i < 2; i++) {
                const float* pir = piB + (size_t)(r0 + i * 8) * SIXH_ + c0;
#pragma unroll
                for (int g = 0; g < 6; g++)
                    pf[i][g] = *reinterpret_cast<const float2*>(pir + g * H_);
            }
        }

        if (t > 0) {
            int stage = 0;
            for (int kc = 0; kc < 8; kc++) {
                if (kc + 1 < 8) { CP_WAIT(1); } else { CP_WAIT(0); }
                BAR_SYNC(1 + kh, 256);
                if (kc + 2 < 8) {
                    int s2 = stage - 1; if (s2 < 0) s2 += 3;
                    load_hchunk(kc + 2, s2, Hhi, Hlo);
                }

                const uint32_t hb_hi = sb + SM_H2_OFF + (kh * 3 + stage) * HS2_BUFB;
                const uint32_t hb_lo = hb_hi + HS2_TILEB;

#pragma unroll
                for (int ks = 0; ks < 2; ks++) {
                    uint32_t ahi[4], alo[4];
                    uint32_t aoff = abase + ks * 32;
                    ldsm4(ahi, hb_hi + aoff);
                    ldsm4(alo, hb_lo + aoff);
                    const uint32_t kline = klbase + kc * 4 + ks * 2 + lhalf;
#pragma unroll
                    for (int p = 0; p < 3; p++) {
                        uint32_t bh[4], bl[4];
                        uint32_t boff = browbase[p] + ((kline ^ brow7[p]) * 16);
                        ldsm4(bh, sb + boff);
                        ldsm4(bl, sb + WS2_TILEB + boff);
                        const int qmax = (p == 2) ? 1 : 2;
#pragma unroll
                        for (int q = 0; q < qmax; q++) {
                            const int g = 2 * p + q;
                            uint32_t bhf[2] = {bh[q], bh[q + 2]};
                            uint32_t blf[2] = {bl[q], bl[q + 2]};
                            mma16816(acc[g], ahi, bhf);
                            mma16816(acc[g], ahi, blf);
                            mma16816(acc[g], alo, bhf);
                        }
                    }
                }
                if (++stage == 3) stage = 0;
            }

            // ---- K-split reduction: upper half -> smem -> lower half adds
            __syncthreads();
            if (kh == 1) {
                float* e = ex + (size_t)t256 * 20;
#pragma unroll
                for (int g = 0; g < 5; g++)
                    *reinterpret_cast<float4*>(e + g * 4) =
                        *reinterpret_cast<float4*>(&acc[g][0]);
            }
            __syncthreads();
            if (kh == 0) {
                const float* e = ex + (size_t)t256 * 20;
#pragma unroll
                for (int g = 0; g < 5; g++) {
                    float4 v = *reinterpret_cast<const float4*>(e + g * 4);
                    acc[g][0] += v.x; acc[g][1] += v.y;
                    acc[g][2] += v.z; acc[g][3] += v.w;
                }
            }
        }

        // ---- epilogue (lower half): gates + cell + highway + dropout
        if (kh == 0) {
            __nv_bfloat16* __restrict__ hhi = g_Hallhi + (size_t)t * B_ * H_;
            __nv_bfloat16* __restrict__ hlo = g_Halllo + (size_t)t * B_ * H_;
#pragma unroll
            for (int i = 0; i < 2; i++) {
                const int r = r0 + i * 8;
                float igx = sigmoidf_(pf[i][0].x + acc[0][2 * i + 0] + bs2[0].x);
                float igy = sigmoidf_(pf[i][0].y + acc[0][2 * i + 1] + bs2[0].y);
                float fgx = sigmoidf_(pf[i][1].x + acc[1][2 * i + 0] + bs2[1].x);
                float fgy = sigmoidf_(pf[i][1].y + acc[1][2 * i + 1] + bs2[1].y);
                float mix = tanhf   (pf[i][2].x + acc[2][2 * i + 0] + bs2[2].x);
                float miy = tanhf   (pf[i][2].y + acc[2][2 * i + 1] + bs2[2].y);
                float ogx = sigmoidf_(pf[i][3].x + acc[3][2 * i + 0] + bs2[3].x);
                float ogy = sigmoidf_(pf[i][3].y + acc[3][2 * i + 1] + bs2[3].y);
                float hgx = sigmoidf_(pf[i][4].x + acc[4][2 * i + 0] + bs2[4].x);
                float hgy = sigmoidf_(pf[i][4].y + acc[4][2 * i + 1] + bs2[4].y);

                float cnx = igx * mix + fgx * cst[i].x;
                float cny = igy * miy + fgy * cst[i].y;
                float ox = ogx * tanhf(cnx);
                float oy = ogy * tanhf(cny);
                ox = hgx * ox + (1.f - hgx) * pf[i][5].x;
                oy = hgy * oy + (1.f - hgy) * pf[i][5].y;
                ox *= mk[i].x;
                oy *= mk[i].y;
                cst[i].x = cnx;
                cst[i].y = cny;

                __nv_bfloat16 hx = __float2bfloat16_rn(ox);
                __nv_bfloat16 hy = __float2bfloat16_rn(oy);
                __nv_bfloat16 lx = __float2bfloat16_rn(ox - __bfloat162float(hx));
                __nv_bfloat16 ly = __float2bfloat16_rn(oy - __bfloat162float(hy));
                uint32_t ph = (uint32_t)__bfloat16_as_ushort(hy) << 16 | __bfloat16_as_ushort(hx);
                uint32_t pl = (uint32_t)__bfloat16_as_ushort(ly) << 16 | __bfloat16_as_ushort(lx);
                *reinterpret_cast<uint32_t*>(hhi + (size_t)r * H_ + c0) = ph;
                *reinterpret_cast<uint32_t*>(hlo + (size_t)r * H_ + c0) = pl;
            }
        }

        // ---- per-group barrier: monotonic counter, one hop
        if (t < T_ - 1) {
            __syncthreads();
            if (tid == 0) {
                __threadfence();
                atomicAdd(p_cnt, 1);
                unsigned target = base + 32u * (unsigned)(t + 1);
                unsigned v;
                do {
                    asm volatile("ld.acquire.gpu.global.u32 %0, [%1];"
                                 : "=r"(v) : "l"(p_cnt));
                } while ((int)(v - target) < 0);
            }
            __syncthreads();
        }
    }
}

// ---------------------------------------------------------------------------
// kernel_launch
// Input order: x, labels, embed, Wi, bi, Ws, bs, Wo, bo, mask
// ---------------------------------------------------------------------------
extern "C" void kernel_launch(void* const* d_in, const int* in_sizes, int n_in,
                              void* d_out, int out_size) {
    const float* x      = (const float*)d_in[0];
    const int*   labels = (const int*)  d_in[1];
    const float* embed  = (const float*)d_in[2];
    const float* Wi     = (const float*)d_in[3];
    const float* bi     = (const float*)d_in[4];
    const float* Ws     = (const float*)d_in[5];
    const float* bs     = (const float*)d_in[6];
    const float* Wo     = (const float*)d_in[7];
    const float* bo     = (const float*)d_in[8];
    const float* mask   = (const float*)d_in[9];
    float* out = (float*)d_out;

    __nv_bfloat16 *tihi, *tilo, *wihi, *wilo, *wohi, *wolo, *hhi, *hlo;
    float* pi;
    cudaGetSymbolAddress((void**)&tihi, g_TIhi);
    cudaGetSymbolAddress((void**)&tilo, g_TIlo);
    cudaGetSymbolAddress((void**)&wihi, g_Wihi);
    cudaGetSymbolAddress((void**)&wilo, g_Wilo);
    cudaGetSymbolAddress((void**)&wohi, g_Wohi);
    cudaGetSymbolAddress((void**)&wolo, g_Wolo);
    cudaGetSymbolAddress((void**)&hhi,  g_Hallhi);
    cudaGetSymbolAddress((void**)&hlo,  g_Halllo);
    cudaGetSymbolAddress((void**)&pi,   g_PI);

    // 1) merged prep (Wi split + Wo split + concat/split)
    k_prep<<<(NPREP_ + 255) / 256, 256>>>(x, labels, embed, Wi, Wo);

    // 2) PI = TI @ Wi^T + bi  (R14/R15 GEMM — best measured)
    {
        const int smem_bytes = SMOFF_ + 2 * STG_;   // 1024 + 48KB
        cudaFuncSetAttribute(k_mmaG<KIN_, SIXH_, false>,
                             cudaFuncAttributeMaxDynamicSharedMemorySize, smem_bytes);
        dim3 grid((M_TOT / 64) * (SIXH_ / 128));    // 6144
        k_mmaG<KIN_, SIXH_, false><<<grid, 128, smem_bytes>>>(
            tihi, tilo, wihi, wilo, bi, pi, SIXH_ / 128);
    }
    // 3) persistent recurrence (R9 pipeline, one-hop barrier)
    {
        cudaFuncSetAttribute(k_recur_mma, cudaFuncAttributeMaxDynamicSharedMemorySize, SMEM_RECUR2);
        k_recur_mma<<<NCTA_, 512, SMEM_RECUR2>>>(Ws, bs, mask);
    }
    // 4) OUT = H_all @ Wo^T + bo
    {
        const int smem_bytes = SMOFF_ + 2 * STG_;
        cudaFuncSetAttribute(k_mmaG<H_, NC_, true>,
                             cudaFuncAttributeMaxDynamicSharedMemorySize, smem_bytes);
        dim3 grid((M_TOT / 64) * 2);                // 512
        k_mmaG<H_, NC_, true><<<grid, 128, smem_bytes>>>(
            hhi, hlo, wohi, wolo, bo, out, 2);
    }
}